// round 15
// baseline (speedup 1.0000x reference)
#include <cuda_runtime.h>
#include <cuda_fp16.h>
#include <cstddef>
#include <cstdint>

// ---------------------------------------------------------------------------
// Problem constants: B=4, S=8192, D=512, H=8, HD=64, W=128.
// MT = 32768 tokens, 256 windows of 128.
// ---------------------------------------------------------------------------
#define MT 32768
#define DD 512
#define D3 1536
#define DF 2048

// ---------------------------------------------------------------------------
// Scratch (device globals — allocation-free per harness rules)
// ---------------------------------------------------------------------------
__device__ float g_x1  [(size_t)MT * DD];     // f32 ln1 output (FFN residual)
__device__ float g_resb[(size_t)MT * DD];     // f32 pre-LN buffer

// fp16 planes
__device__ __half g_qh [(size_t)MT * D3];   // qkv (fp16, QKV-GEMM output)
__device__ __half g_sh [(size_t)MT * DD];   // src
__device__ __half g_ah [(size_t)MT * DD];   // attn out
__device__ __half g_xh [(size_t)MT * DD];   // ln1 out
__device__ __half g_fh [(size_t)MT * DF];   // ffn mid
__device__ __half g_wq [D3 * DD];
__device__ __half g_wo [DD * DD];
__device__ __half g_w1 [DF * DD];
__device__ __half g_w2 [DD * DF];

// ---------------------------------------------------------------------------
// PTX helpers (plain-compute_103 features: cp.async / ldmatrix / mma.sync)
// ---------------------------------------------------------------------------
__device__ __forceinline__ uint32_t cvta_s(const void* p) {
    uint32_t a;
    asm("{ .reg .u64 t; cvta.to.shared.u64 t, %1; cvt.u32.u64 %0, t; }"
        : "=r"(a) : "l"(p));
    return a;
}
__device__ __forceinline__ void cp16(uint32_t dst, const void* src) {
    asm volatile("cp.async.cg.shared.global [%0], [%1], 16;"
                 :: "r"(dst), "l"(src));
}
__device__ __forceinline__ void ldsm_x4(uint32_t* r, uint32_t addr) {
    asm volatile("ldmatrix.sync.aligned.m8n8.x4.shared.b16 {%0,%1,%2,%3}, [%4];"
                 : "=r"(r[0]), "=r"(r[1]), "=r"(r[2]), "=r"(r[3]) : "r"(addr));
}
__device__ __forceinline__ void mma_f16(float* d, const uint32_t* a,
                                        const uint32_t* b) {
    asm volatile(
        "mma.sync.aligned.m16n8k16.row.col.f32.f16.f16.f32 "
        "{%0,%1,%2,%3}, {%4,%5,%6,%7}, {%8,%9}, {%0,%1,%2,%3};"
        : "+f"(d[0]), "+f"(d[1]), "+f"(d[2]), "+f"(d[3])
        : "r"(a[0]), "r"(a[1]), "r"(a[2]), "r"(a[3]), "r"(b[0]), "r"(b[1]));
}

__device__ __forceinline__ uint32_t pack_h2(float a, float b) {
    return (uint32_t)__half_as_ushort(__float2half(a))
         | ((uint32_t)__half_as_ushort(__float2half(b)) << 16);
}

// ---------------------------------------------------------------------------
// HMMA fp16 1-pass GEMM: C = A*B^T + bias (+ epilogue)
//   CTA tile 128(M) x 256(N), BK=64 (128B rows, XOR swizzle), 2-stage
//   cp.async, 512 threads / 16 warps (2M x 8N), warp tile 64x32 — per-warp
//   fragment/MMA/epilogue algebra byte-identical to the PROVEN R13/R14 kernel.
//   EPI 0: bias -> f32    EPI 1: bias+ReLU -> fp16   EPI 2: bias+res -> f32
//   EPI 3: bias -> fp16
// ---------------------------------------------------------------------------
static constexpr int STAGE = 49152;   // A 16K | B 32K

__device__ __forceinline__ void load_chunk(
    const __half* __restrict__ Ap, const __half* __restrict__ Bp,
    int m0, int n0, int K, int k0, int tid, uint32_t sb)
{
#pragma unroll
    for (int j = 0; j < 2; j++) {                 // A: 128 rows x 8 x 16B
        int id  = tid + 512 * j;                  // 0..1023
        int row = id >> 3, c = id & 7;
        uint32_t soff = (uint32_t)(row * 128 + ((c ^ (row & 7)) << 4));
        cp16(sb + soff, Ap + (size_t)(m0 + row) * K + k0 + c * 8);
    }
#pragma unroll
    for (int j = 0; j < 4; j++) {                 // B: 256 rows x 8 x 16B
        int id  = tid + 512 * j;                  // 0..2047
        int row = id >> 3, c = id & 7;
        uint32_t soff = (uint32_t)(row * 128 + ((c ^ (row & 7)) << 4));
        cp16(sb + 16384 + soff, Bp + (size_t)(n0 + row) * K + k0 + c * 8);
    }
    asm volatile("cp.async.commit_group;" ::: "memory");
}

template <int EPI>
__global__ void __launch_bounds__(512)
tc_gemm(const __half* __restrict__ Ap, const __half* __restrict__ Bp,
        const float* __restrict__ bias, const float* __restrict__ res,
        float* __restrict__ Cf, __half* __restrict__ Ch,
        int N, int K)
{
    extern __shared__ __align__(1024) char dyn_smem[];
    uint32_t sbase = (cvta_s(dyn_smem) + 1023u) & ~1023u;

    const int tid  = threadIdx.x;
    const int lane = tid & 31;
    const int w    = tid >> 5;            // 0..15
    const int wm   = w & 1;               // 0..1  (M)
    const int wn   = w >> 1;              // 0..7  (N)
    const int m0   = blockIdx.y * 128;
    const int n0   = blockIdx.x * 256;

    float acc[4][4][4];
#pragma unroll
    for (int i = 0; i < 4; i++)
#pragma unroll
        for (int j = 0; j < 4; j++)
#pragma unroll
            for (int c = 0; c < 4; c++) acc[i][j][c] = 0.0f;

    const int nk = K >> 6;
    load_chunk(Ap, Bp, m0, n0, K, 0, tid, sbase);

    // ldmatrix lane->address maps (identical to validated R13/R14 kernels)
    const int am   = wm * 64 + (lane & 15);                       // + mt*16
    const int acb  = (lane >> 4);                                 // k-half
    const int bn   = wn * 32 + (lane & 7) + ((lane >> 4) << 3);   // + bt*16
    const int bcb  = (lane >> 3) & 1;

    for (int i = 0; i < nk; i++) {
        if (i + 1 < nk) {
            load_chunk(Ap, Bp, m0, n0, K, (i + 1) << 6, tid,
                       sbase + (uint32_t)((i + 1) & 1) * STAGE);
            asm volatile("cp.async.wait_group 1;" ::: "memory");
        } else {
            asm volatile("cp.async.wait_group 0;" ::: "memory");
        }
        __syncthreads();

        const uint32_t sA = sbase + (uint32_t)(i & 1) * STAGE;
        const uint32_t sB = sA + 16384;

#pragma unroll
        for (int ks = 0; ks < 4; ks++) {
            uint32_t ahf[4][4];
#pragma unroll
            for (int mt = 0; mt < 4; mt++) {
                int m = am + mt * 16;
                int c = ks * 2 + acb;
                uint32_t off = (uint32_t)(m * 128 + ((c ^ (m & 7)) << 4));
                ldsm_x4(ahf[mt], sA + off);
            }
            uint32_t bhf[2][4];
#pragma unroll
            for (int bt = 0; bt < 2; bt++) {
                int n = bn + bt * 16;
                int c = ks * 2 + bcb;
                uint32_t off = (uint32_t)(n * 128 + ((c ^ (n & 7)) << 4));
                ldsm_x4(bhf[bt], sB + off);     // non-trans: [n][k] == A layout
            }
#pragma unroll
            for (int mt = 0; mt < 4; mt++)
#pragma unroll
                for (int nt = 0; nt < 4; nt++)
                    mma_f16(acc[mt][nt], ahf[mt], &bhf[nt >> 1][(nt & 1) * 2]);
        }
        __syncthreads();
    }

    // ---- epilogue: c0=(g,2t) c1=(g,2t+1) c2=(g+8,2t) c3=(g+8,2t+1) ----
    const int gq = lane >> 2;
    const int tq = lane & 3;
#pragma unroll
    for (int mt = 0; mt < 4; mt++)
#pragma unroll
        for (int nt = 0; nt < 4; nt++) {
            const int n  = n0 + wn * 32 + nt * 8 + tq * 2;
            const float b0 = bias[n], b1 = bias[n + 1];
#pragma unroll
            for (int half = 0; half < 2; half++) {
                const int m  = m0 + wm * 64 + mt * 16 + gq + half * 8;
                float v0 = acc[mt][nt][half * 2 + 0] + b0;
                float v1 = acc[mt][nt][half * 2 + 1] + b1;
                const size_t off = (size_t)m * N + n;
                if (EPI == 2) {
                    float2 r2 = *(const float2*)(res + off);
                    v0 += r2.x; v1 += r2.y;
                }
                if (EPI == 1) {
                    v0 = fmaxf(v0, 0.0f); v1 = fmaxf(v1, 0.0f);
                    *(uint32_t*)(Ch + off) = pack_h2(v0, v1);
                } else if (EPI == 3) {
                    *(uint32_t*)(Ch + off) = pack_h2(v0, v1);
                } else {
                    *(float2*)(Cf + off) = make_float2(v0, v1);
                }
            }
        }
}

// ---------------------------------------------------------------------------
// f32 -> single fp16 plane conversion
// ---------------------------------------------------------------------------
__global__ void __launch_bounds__(256)
cvtw_kernel(const float* __restrict__ x, __half* __restrict__ hp, int n4)
{
    int i = blockIdx.x * 256 + threadIdx.x;
    if (i >= n4) return;
    float4 v = ((const float4*)x)[i];
    ((uint2*)hp)[i] = make_uint2(pack_h2(v.x, v.y), pack_h2(v.z, v.w));
}

// ---------------------------------------------------------------------------
// HMMA windowed attention (PROVEN R14). Grid (256 windows, 8 heads),
// 256 threads (8 warps, 16 query rows each). fp16 qkv in, fp16 attn out.
// ---------------------------------------------------------------------------
#define VT_STR 272
#define ATT_SMEM (32768 + 64 * VT_STR)   // Q 16K | K 16K | Vt 17KB

__global__ void __launch_bounds__(256)
attn_kernel(const __half* __restrict__ qkv, __half* __restrict__ oh)
{
    extern __shared__ __align__(1024) char asmem[];
    const uint32_t sb = cvta_s(asmem);
    const uint32_t Qs = sb, Ks = sb + 16384, Vt = sb + 32768;

    const int tid  = threadIdx.x;
    const int lane = tid & 31;
    const int w    = tid >> 5;
    const int win  = blockIdx.x;
    const int h    = blockIdx.y;
    const size_t tb = (size_t)win * 128 * D3 + h * 64;   // half-element base

    // Q,K cooperative cp.async loads (swizzled 128B rows)
#pragma unroll
    for (int it = 0; it < 4; it++) {
        int u = it * 256 + tid;          // 0..1023
        int row = u >> 3, c = u & 7;
        uint32_t soff = (uint32_t)(row * 128 + ((c ^ (row & 7)) << 4));
        const __half* qg = qkv + tb + (size_t)row * D3 + c * 8;
        cp16(Qs + soff, qg);
        cp16(Ks + soff, qg + 512);
    }
    asm volatile("cp.async.commit_group;" ::: "memory");

    // V transpose into Vt[n][k]
#pragma unroll
    for (int it = 0; it < 8; it++) {
        int u = it * 256 + tid;          // 0..2047 uint2 units
        int k = u >> 4, nq = (u & 15) << 2;
        uint2 vv = *(const uint2*)(qkv + tb + (size_t)k * D3 + 1024 + nq);
        const __half* hp = (const __half*)&vv;
#pragma unroll
        for (int j = 0; j < 4; j++)
            *(__half*)(asmem + 32768 + (nq + j) * VT_STR + k * 2) = hp[j];
    }
    asm volatile("cp.async.wait_group 0;" ::: "memory");
    __syncthreads();

    // ---- S = Q K^T ----
    float s[16][4];
#pragma unroll
    for (int t = 0; t < 16; t++)
#pragma unroll
        for (int c = 0; c < 4; c++) s[t][c] = 0.0f;

    const int am  = w * 16 + (lane & 15);
    const int acb = lane >> 4;
    const int bn8 = (lane & 7) + ((lane >> 4) << 3);
    const int bcb = (lane >> 3) & 1;

#pragma unroll
    for (int ks = 0; ks < 4; ks++) {
        uint32_t a[4];
        {
            int c = ks * 2 + acb;
            ldsm_x4(a, Qs + (uint32_t)(am * 128 + ((c ^ (am & 7)) << 4)));
        }
#pragma unroll
        for (int jp = 0; jp < 8; jp++) {
            uint32_t b[4];
            int n = jp * 16 + bn8;
            int c = ks * 2 + bcb;
            ldsm_x4(b, Ks + (uint32_t)(n * 128 + ((c ^ (n & 7)) << 4)));
            mma_f16(s[2 * jp],     a, b);
            mma_f16(s[2 * jp + 1], a, b + 2);
        }
    }

    // ---- softmax ----
    float m0 = -1e30f, m1 = -1e30f;
#pragma unroll
    for (int t = 0; t < 16; t++) {
        m0 = fmaxf(m0, fmaxf(s[t][0], s[t][1]));
        m1 = fmaxf(m1, fmaxf(s[t][2], s[t][3]));
    }
    m0 = fmaxf(m0, __shfl_xor_sync(0xffffffffu, m0, 1));
    m0 = fmaxf(m0, __shfl_xor_sync(0xffffffffu, m0, 2));
    m1 = fmaxf(m1, __shfl_xor_sync(0xffffffffu, m1, 1));
    m1 = fmaxf(m1, __shfl_xor_sync(0xffffffffu, m1, 2));

    float sum0 = 0.0f, sum1 = 0.0f;
#pragma unroll
    for (int t = 0; t < 16; t++) {
        s[t][0] = __expf((s[t][0] - m0) * 0.125f); sum0 += s[t][0];
        s[t][1] = __expf((s[t][1] - m0) * 0.125f); sum0 += s[t][1];
        s[t][2] = __expf((s[t][2] - m1) * 0.125f); sum1 += s[t][2];
        s[t][3] = __expf((s[t][3] - m1) * 0.125f); sum1 += s[t][3];
    }
    sum0 += __shfl_xor_sync(0xffffffffu, sum0, 1);
    sum0 += __shfl_xor_sync(0xffffffffu, sum0, 2);
    sum1 += __shfl_xor_sync(0xffffffffu, sum1, 1);
    sum1 += __shfl_xor_sync(0xffffffffu, sum1, 2);
    const float inv0 = 1.0f / sum0, inv1 = 1.0f / sum1;
#pragma unroll
    for (int t = 0; t < 16; t++) {
        s[t][0] *= inv0; s[t][1] *= inv0;
        s[t][2] *= inv1; s[t][3] *= inv1;
    }

    // ---- O = P V ----
    float o[8][4];
#pragma unroll
    for (int t = 0; t < 8; t++)
#pragma unroll
        for (int c = 0; c < 4; c++) o[t][c] = 0.0f;

#pragma unroll
    for (int kc = 0; kc < 8; kc++) {
        uint32_t a[4];
        a[0] = pack_h2(s[2 * kc][0],     s[2 * kc][1]);
        a[1] = pack_h2(s[2 * kc][2],     s[2 * kc][3]);
        a[2] = pack_h2(s[2 * kc + 1][0], s[2 * kc + 1][1]);
        a[3] = pack_h2(s[2 * kc + 1][2], s[2 * kc + 1][3]);
#pragma unroll
        for (int bp = 0; bp < 4; bp++) {
            uint32_t b[4];
            int n = bp * 16 + bn8;
            int c = kc * 2 + bcb;
            ldsm_x4(b, Vt + (uint32_t)(n * VT_STR + c * 16));
            mma_f16(o[2 * bp],     a, b);
            mma_f16(o[2 * bp + 1], a, b + 2);
        }
    }

    // ---- store fp16 attn output ----
    const int gq = lane >> 2, tq = lane & 3;
#pragma unroll
    for (int nt = 0; nt < 8; nt++) {
        const int n = nt * 8 + tq * 2;
#pragma unroll
        for (int half = 0; half < 2; half++) {
            const int row = w * 16 + gq + half * 8;
            const size_t off = ((size_t)win * 128 + row) * DD + h * 64 + n;
            *(uint32_t*)(oh + off) = pack_h2(o[nt][half * 2], o[nt][half * 2 + 1]);
        }
    }
}

// ---------------------------------------------------------------------------
// LayerNorm over D=512 (1 row per 128-thread block).  HL=true also emits a
// single fp16 plane for the following GEMM.
// ---------------------------------------------------------------------------
template <bool HL>
__global__ void __launch_bounds__(128)
ln_kernel(const float* __restrict__ x, const float* __restrict__ g,
          const float* __restrict__ b, float* __restrict__ outf,
          __half* __restrict__ oh)
{
    __shared__ float red[8];
    const int row = blockIdx.x;
    const int tid = threadIdx.x;
    const int lane = tid & 31, wid = tid >> 5;

    float4 v = *(const float4*)(x + (size_t)row * DD + tid * 4);
    float s = v.x + v.y + v.z + v.w;
#pragma unroll
    for (int o = 16; o > 0; o >>= 1) s += __shfl_xor_sync(0xffffffffu, s, o);
    if (lane == 0) red[wid] = s;
    __syncthreads();
    if (tid == 0) red[0] = red[0] + red[1] + red[2] + red[3];
    __syncthreads();
    const float mu = red[0] * (1.0f / 512.0f);

    const float d0 = v.x - mu, d1 = v.y - mu, d2 = v.z - mu, d3 = v.w - mu;
    float sq = d0*d0 + d1*d1 + d2*d2 + d3*d3;
#pragma unroll
    for (int o = 16; o > 0; o >>= 1) sq += __shfl_xor_sync(0xffffffffu, sq, o);
    __syncthreads();
    if (lane == 0) red[wid] = sq;
    __syncthreads();
    if (tid == 0) red[0] = red[0] + red[1] + red[2] + red[3];
    __syncthreads();
    const float inv = rsqrtf(red[0] * (1.0f / 512.0f) + 1e-5f);

    float4 gg = *(const float4*)(g + tid * 4);
    float4 bb = *(const float4*)(b + tid * 4);
    const float y0 = d0 * inv * gg.x + bb.x;
    const float y1 = d1 * inv * gg.y + bb.y;
    const float y2 = d2 * inv * gg.z + bb.z;
    const float y3 = d3 * inv * gg.w + bb.w;
    *(float4*)(outf + (size_t)row * DD + tid * 4) = make_float4(y0, y1, y2, y3);
    if (HL) {
        const size_t i = (size_t)row * 128 + tid;
        ((uint2*)oh)[i] = make_uint2(pack_h2(y0, y1), pack_h2(y2, y3));
    }
}

// ---------------------------------------------------------------------------
// Launch pipeline (graph-capturable)
// ---------------------------------------------------------------------------
extern "C" void kernel_launch(void* const* d_in, const int* in_sizes, int n_in,
                              void* d_out, int out_size)
{
    (void)in_sizes; (void)n_in; (void)out_size;
    const float* src  = (const float*)d_in[0];
    const float* wqkv = (const float*)d_in[1];
    const float* bqkv = (const float*)d_in[2];
    const float* wout = (const float*)d_in[3];
    const float* bout = (const float*)d_in[4];
    const float* ln1g = (const float*)d_in[5];
    const float* ln1b = (const float*)d_in[6];
    const float* w1   = (const float*)d_in[7];
    const float* b1   = (const float*)d_in[8];
    const float* w2   = (const float*)d_in[9];
    const float* b2   = (const float*)d_in[10];
    const float* ln2g = (const float*)d_in[11];
    const float* ln2b = (const float*)d_in[12];
    float* out = (float*)d_out;

    float *x1, *resb;
    __half *qh, *sh, *ah, *xh, *fh, *wq, *wo, *wu, *wd;
    cudaGetSymbolAddress((void**)&x1,   g_x1);
    cudaGetSymbolAddress((void**)&resb, g_resb);
    cudaGetSymbolAddress((void**)&qh,  g_qh);
    cudaGetSymbolAddress((void**)&sh,  g_sh);
    cudaGetSymbolAddress((void**)&ah,  g_ah);
    cudaGetSymbolAddress((void**)&xh,  g_xh);
    cudaGetSymbolAddress((void**)&fh,  g_fh);
    cudaGetSymbolAddress((void**)&wq,  g_wq);  cudaGetSymbolAddress((void**)&wo,  g_wo);
    cudaGetSymbolAddress((void**)&wu,  g_w1);  cudaGetSymbolAddress((void**)&wd,  g_w2);

    const int GEMM_SMEM = 2 * STAGE + 1024;
    cudaFuncSetAttribute(tc_gemm<1>, cudaFuncAttributeMaxDynamicSharedMemorySize, GEMM_SMEM);
    cudaFuncSetAttribute(tc_gemm<2>, cudaFuncAttributeMaxDynamicSharedMemorySize, GEMM_SMEM);
    cudaFuncSetAttribute(tc_gemm<3>, cudaFuncAttributeMaxDynamicSharedMemorySize, GEMM_SMEM);
    cudaFuncSetAttribute(attn_kernel, cudaFuncAttributeMaxDynamicSharedMemorySize, ATT_SMEM);

    // 0) conversions: src + weights -> fp16 planes
    cvtw_kernel<<<(MT * DD / 4 + 255) / 256, 256>>>(src,  sh, MT * DD / 4);
    cvtw_kernel<<<(D3 * DD / 4 + 255) / 256, 256>>>(wqkv, wq, D3 * DD / 4);
    cvtw_kernel<<<(DD * DD / 4 + 255) / 256, 256>>>(wout, wo, DD * DD / 4);
    cvtw_kernel<<<(DF * DD / 4 + 255) / 256, 256>>>(w1,   wu, DF * DD / 4);
    cvtw_kernel<<<(DD * DF / 4 + 255) / 256, 256>>>(w2,   wd, DD * DF / 4);

    // 1) QKV projection -> fp16 qkv
    tc_gemm<3><<<dim3(D3 / 256, MT / 128), 512, GEMM_SMEM>>>(
        sh, wq, bqkv, nullptr, nullptr, qh, D3, DD);
    // 2) HMMA windowed attention -> attn fp16 plane
    attn_kernel<<<dim3(MT / 128, 8), 256, ATT_SMEM>>>(qh, ah);
    // 3) out projection + residual(src) -> resb f32
    tc_gemm<2><<<dim3(DD / 256, MT / 128), 512, GEMM_SMEM>>>(
        ah, wo, bout, src, resb, nullptr, DD, DD);
    // 4) LayerNorm 1 -> x1 f32 + fp16 plane
    ln_kernel<true><<<MT, 128>>>(resb, ln1g, ln1b, x1, xh);
    // 5) FFN up + ReLU -> ff fp16 plane
    tc_gemm<1><<<dim3(DF / 256, MT / 128), 512, GEMM_SMEM>>>(
        xh, wu, b1, nullptr, nullptr, fh, DF, DD);
    // 6) FFN down + residual(x1) -> resb f32
    tc_gemm<2><<<dim3(DD / 256, MT / 128), 512, GEMM_SMEM>>>(
        fh, wd, b2, x1, resb, nullptr, DD, DF);
    // 7) LayerNorm 2 -> output
    ln_kernel<false><<<MT, 128>>>(resb, ln2g, ln2b, out, nullptr);
}

// round 16
// speedup vs baseline: 1.1852x; 1.1852x over previous
#include <cuda_runtime.h>
#include <cuda_fp16.h>
#include <cstddef>
#include <cstdint>

// ---------------------------------------------------------------------------
// Problem constants: B=4, S=8192, D=512, H=8, HD=64, W=128.
// MT = 32768 tokens, 256 windows of 128.
// ---------------------------------------------------------------------------
#define MT 32768
#define DD 512
#define D3 1536
#define DF 2048

// ---------------------------------------------------------------------------
// Scratch (device globals — allocation-free per harness rules)
// ---------------------------------------------------------------------------
__device__ float g_x1  [(size_t)MT * DD];     // f32 ln1 output (FFN residual)
__device__ float g_resb[(size_t)MT * DD];     // f32 pre-LN buffer

// fp16 planes
__device__ __half g_qh [(size_t)MT * D3];   // qkv (fp16, QKV-GEMM output)
__device__ __half g_sh [(size_t)MT * DD];   // src
__device__ __half g_ah [(size_t)MT * DD];   // attn out
__device__ __half g_xh [(size_t)MT * DD];   // ln1 out
__device__ __half g_fh [(size_t)MT * DF];   // ffn mid
__device__ __half g_wq [D3 * DD];
__device__ __half g_wo [DD * DD];
__device__ __half g_w1 [DF * DD];
__device__ __half g_w2 [DD * DF];

// ---------------------------------------------------------------------------
// PTX helpers (plain-compute_103 features: cp.async / ldmatrix / mma.sync)
// ---------------------------------------------------------------------------
__device__ __forceinline__ uint32_t cvta_s(const void* p) {
    uint32_t a;
    asm("{ .reg .u64 t; cvta.to.shared.u64 t, %1; cvt.u32.u64 %0, t; }"
        : "=r"(a) : "l"(p));
    return a;
}
__device__ __forceinline__ void cp16(uint32_t dst, const void* src) {
    asm volatile("cp.async.cg.shared.global [%0], [%1], 16;"
                 :: "r"(dst), "l"(src));
}
__device__ __forceinline__ void ldsm_x4(uint32_t* r, uint32_t addr) {
    asm volatile("ldmatrix.sync.aligned.m8n8.x4.shared.b16 {%0,%1,%2,%3}, [%4];"
                 : "=r"(r[0]), "=r"(r[1]), "=r"(r[2]), "=r"(r[3]) : "r"(addr));
}
__device__ __forceinline__ void mma_f16(float* d, const uint32_t* a,
                                        const uint32_t* b) {
    asm volatile(
        "mma.sync.aligned.m16n8k16.row.col.f32.f16.f16.f32 "
        "{%0,%1,%2,%3}, {%4,%5,%6,%7}, {%8,%9}, {%0,%1,%2,%3};"
        : "+f"(d[0]), "+f"(d[1]), "+f"(d[2]), "+f"(d[3])
        : "r"(a[0]), "r"(a[1]), "r"(a[2]), "r"(a[3]), "r"(b[0]), "r"(b[1]));
}

__device__ __forceinline__ uint32_t pack_h2(float a, float b) {
    return (uint32_t)__half_as_ushort(__float2half(a))
         | ((uint32_t)__half_as_ushort(__float2half(b)) << 16);
}

// ---------------------------------------------------------------------------
// HMMA fp16 1-pass GEMM: C = A*B^T + bias (+ epilogue)
//   R14-PROVEN geometry: CTA tile 128x128, BK=64 (128B rows, XOR swizzle),
//   256 threads / 8 warps (2M x 4N), warp tile 64x32.
//   NEW: 3-stage cp.async pipeline, ONE __syncthreads per k-chunk.
//   Safety: compute(i) reads buf i%3; load(i+2) writes buf (i+2)%3 and is
//   issued only after sync(i), which all warps reach only after finishing
//   compute(i-1) on that very buffer.
//   EPI 0: bias -> f32    EPI 1: bias+ReLU -> fp16   EPI 2: bias+res -> f32
//   EPI 3: bias -> fp16
// ---------------------------------------------------------------------------
static constexpr int STAGE = 32768;   // A 16K | B 16K

__device__ __forceinline__ void load_chunk(
    const __half* __restrict__ Ap, const __half* __restrict__ Bp,
    int m0, int n0, int K, int k0, int tid, uint32_t sb)
{
#pragma unroll
    for (int j = 0; j < 4; j++) {
        int id  = tid + 256 * j;          // 0..1023
        int row = id >> 3;                // 0..127
        int c   = id & 7;                 // 16B chunk within 128B row
        uint32_t soff = (uint32_t)(row * 128 + ((c ^ (row & 7)) << 4));
        size_t ga = (size_t)(m0 + row) * K + k0 + c * 8;
        size_t gb = (size_t)(n0 + row) * K + k0 + c * 8;
        cp16(sb + soff,          Ap + ga);
        cp16(sb + 16384 + soff,  Bp + gb);
    }
    asm volatile("cp.async.commit_group;" ::: "memory");
}

template <int EPI>
__global__ void __launch_bounds__(256)
tc_gemm(const __half* __restrict__ Ap, const __half* __restrict__ Bp,
        const float* __restrict__ bias, const float* __restrict__ res,
        float* __restrict__ Cf, __half* __restrict__ Ch,
        int N, int K)
{
    extern __shared__ __align__(1024) char dyn_smem[];
    uint32_t sbase = (cvta_s(dyn_smem) + 1023u) & ~1023u;

    const int tid  = threadIdx.x;
    const int lane = tid & 31;
    const int w    = tid >> 5;
    const int wm   = w & 1;               // 0..1  (M)
    const int wn   = w >> 1;              // 0..3  (N)
    const int m0   = blockIdx.y * 128;
    const int n0   = blockIdx.x * 128;

    float acc[4][4][4];
#pragma unroll
    for (int i = 0; i < 4; i++)
#pragma unroll
        for (int j = 0; j < 4; j++)
#pragma unroll
            for (int c = 0; c < 4; c++) acc[i][j][c] = 0.0f;

    const int nk = K >> 6;
    load_chunk(Ap, Bp, m0, n0, K, 0,  tid, sbase);
    load_chunk(Ap, Bp, m0, n0, K, 64, tid, sbase + STAGE);

    // ldmatrix lane->address maps (identical to validated R13/R14 kernels)
    const int am   = wm * 64 + (lane & 15);                       // + mt*16
    const int acb  = (lane >> 4);                                 // k-half
    const int bn   = wn * 32 + (lane & 7) + ((lane >> 4) << 3);   // + bt*16
    const int bcb  = (lane >> 3) & 1;

    for (int i = 0; i < nk; i++) {
        if (i + 1 < nk)
            asm volatile("cp.async.wait_group 1;" ::: "memory");
        else
            asm volatile("cp.async.wait_group 0;" ::: "memory");
        __syncthreads();                  // single barrier per chunk

        const uint32_t sA = sbase + (uint32_t)(i % 3) * STAGE;
        const uint32_t sB = sA + 16384;

#pragma unroll
        for (int ks = 0; ks < 4; ks++) {
            uint32_t ahf[4][4];
#pragma unroll
            for (int mt = 0; mt < 4; mt++) {
                int m = am + mt * 16;
                int c = ks * 2 + acb;
                uint32_t off = (uint32_t)(m * 128 + ((c ^ (m & 7)) << 4));
                ldsm_x4(ahf[mt], sA + off);
            }
            uint32_t bhf[2][4];
#pragma unroll
            for (int bt = 0; bt < 2; bt++) {
                int n = bn + bt * 16;
                int c = ks * 2 + bcb;
                uint32_t off = (uint32_t)(n * 128 + ((c ^ (n & 7)) << 4));
                ldsm_x4(bhf[bt], sB + off);     // non-trans: [n][k] == A layout
            }
#pragma unroll
            for (int mt = 0; mt < 4; mt++)
#pragma unroll
                for (int nt = 0; nt < 4; nt++)
                    mma_f16(acc[mt][nt], ahf[mt], &bhf[nt >> 1][(nt & 1) * 2]);
        }

        if (i + 2 < nk)
            load_chunk(Ap, Bp, m0, n0, K, (i + 2) << 6, tid,
                       sbase + (uint32_t)((i + 2) % 3) * STAGE);
    }

    // ---- epilogue: c0=(g,2t) c1=(g,2t+1) c2=(g+8,2t) c3=(g+8,2t+1) ----
    const int gq = lane >> 2;
    const int tq = lane & 3;
#pragma unroll
    for (int mt = 0; mt < 4; mt++)
#pragma unroll
        for (int nt = 0; nt < 4; nt++) {
            const int n  = n0 + wn * 32 + nt * 8 + tq * 2;
            const float b0 = bias[n], b1 = bias[n + 1];
#pragma unroll
            for (int half = 0; half < 2; half++) {
                const int m  = m0 + wm * 64 + mt * 16 + gq + half * 8;
                float v0 = acc[mt][nt][half * 2 + 0] + b0;
                float v1 = acc[mt][nt][half * 2 + 1] + b1;
                const size_t off = (size_t)m * N + n;
                if (EPI == 2) {
                    float2 r2 = *(const float2*)(res + off);
                    v0 += r2.x; v1 += r2.y;
                }
                if (EPI == 1) {
                    v0 = fmaxf(v0, 0.0f); v1 = fmaxf(v1, 0.0f);
                    *(uint32_t*)(Ch + off) = pack_h2(v0, v1);
                } else if (EPI == 3) {
                    *(uint32_t*)(Ch + off) = pack_h2(v0, v1);
                } else {
                    *(float2*)(Cf + off) = make_float2(v0, v1);
                }
            }
        }
}

// ---------------------------------------------------------------------------
// f32 -> fp16 conversions: one kernel for src, one batched kernel for all
// four weight matrices (saves 3 launch/tail overheads).
// ---------------------------------------------------------------------------
__global__ void __launch_bounds__(256)
cvtw_kernel(const float* __restrict__ x, __half* __restrict__ hp, int n4)
{
    int i = blockIdx.x * 256 + threadIdx.x;
    if (i >= n4) return;
    float4 v = ((const float4*)x)[i];
    ((uint2*)hp)[i] = make_uint2(pack_h2(v.x, v.y), pack_h2(v.z, v.w));
}

__global__ void __launch_bounds__(256)
cvtw4_kernel(const float* __restrict__ w0, __half* __restrict__ h0, int n0,
             const float* __restrict__ w1, __half* __restrict__ h1, int n1,
             const float* __restrict__ w2, __half* __restrict__ h2, int n2,
             const float* __restrict__ w3, __half* __restrict__ h3, int n3)
{
    int i = blockIdx.x * 256 + threadIdx.x;
    const float* x; __half* hp;
    if (i < n0)                 { x = w0; hp = h0; }
    else if ((i -= n0) < n1)    { x = w1; hp = h1; }
    else if ((i -= n1) < n2)    { x = w2; hp = h2; }
    else if ((i -= n2) < n3)    { x = w3; hp = h3; }
    else return;
    float4 v = ((const float4*)x)[i];
    ((uint2*)hp)[i] = make_uint2(pack_h2(v.x, v.y), pack_h2(v.z, v.w));
}

// ---------------------------------------------------------------------------
// HMMA windowed attention (PROVEN R14). Grid (256 windows, 8 heads),
// 256 threads (8 warps, 16 query rows each). fp16 qkv in, fp16 attn out.
// ---------------------------------------------------------------------------
#define VT_STR 272
#define ATT_SMEM (32768 + 64 * VT_STR)   // Q 16K | K 16K | Vt 17KB

__global__ void __launch_bounds__(256)
attn_kernel(const __half* __restrict__ qkv, __half* __restrict__ oh)
{
    extern __shared__ __align__(1024) char asmem[];
    const uint32_t sb = cvta_s(asmem);
    const uint32_t Qs = sb, Ks = sb + 16384, Vt = sb + 32768;

    const int tid  = threadIdx.x;
    const int lane = tid & 31;
    const int w    = tid >> 5;
    const int win  = blockIdx.x;
    const int h    = blockIdx.y;
    const size_t tb = (size_t)win * 128 * D3 + h * 64;   // half-element base

    // Q,K cooperative cp.async loads (swizzled 128B rows)
#pragma unroll
    for (int it = 0; it < 4; it++) {
        int u = it * 256 + tid;          // 0..1023
        int row = u >> 3, c = u & 7;
        uint32_t soff = (uint32_t)(row * 128 + ((c ^ (row & 7)) << 4));
        const __half* qg = qkv + tb + (size_t)row * D3 + c * 8;
        cp16(Qs + soff, qg);
        cp16(Ks + soff, qg + 512);
    }
    asm volatile("cp.async.commit_group;" ::: "memory");

    // V transpose into Vt[n][k]
#pragma unroll
    for (int it = 0; it < 8; it++) {
        int u = it * 256 + tid;          // 0..2047 uint2 units
        int k = u >> 4, nq = (u & 15) << 2;
        uint2 vv = *(const uint2*)(qkv + tb + (size_t)k * D3 + 1024 + nq);
        const __half* hp = (const __half*)&vv;
#pragma unroll
        for (int j = 0; j < 4; j++)
            *(__half*)(asmem + 32768 + (nq + j) * VT_STR + k * 2) = hp[j];
    }
    asm volatile("cp.async.wait_group 0;" ::: "memory");
    __syncthreads();

    // ---- S = Q K^T ----
    float s[16][4];
#pragma unroll
    for (int t = 0; t < 16; t++)
#pragma unroll
        for (int c = 0; c < 4; c++) s[t][c] = 0.0f;

    const int am  = w * 16 + (lane & 15);
    const int acb = lane >> 4;
    const int bn8 = (lane & 7) + ((lane >> 4) << 3);
    const int bcb = (lane >> 3) & 1;

#pragma unroll
    for (int ks = 0; ks < 4; ks++) {
        uint32_t a[4];
        {
            int c = ks * 2 + acb;
            ldsm_x4(a, Qs + (uint32_t)(am * 128 + ((c ^ (am & 7)) << 4)));
        }
#pragma unroll
        for (int jp = 0; jp < 8; jp++) {
            uint32_t b[4];
            int n = jp * 16 + bn8;
            int c = ks * 2 + bcb;
            ldsm_x4(b, Ks + (uint32_t)(n * 128 + ((c ^ (n & 7)) << 4)));
            mma_f16(s[2 * jp],     a, b);
            mma_f16(s[2 * jp + 1], a, b + 2);
        }
    }

    // ---- softmax ----
    float m0 = -1e30f, m1 = -1e30f;
#pragma unroll
    for (int t = 0; t < 16; t++) {
        m0 = fmaxf(m0, fmaxf(s[t][0], s[t][1]));
        m1 = fmaxf(m1, fmaxf(s[t][2], s[t][3]));
    }
    m0 = fmaxf(m0, __shfl_xor_sync(0xffffffffu, m0, 1));
    m0 = fmaxf(m0, __shfl_xor_sync(0xffffffffu, m0, 2));
    m1 = fmaxf(m1, __shfl_xor_sync(0xffffffffu, m1, 1));
    m1 = fmaxf(m1, __shfl_xor_sync(0xffffffffu, m1, 2));

    float sum0 = 0.0f, sum1 = 0.0f;
#pragma unroll
    for (int t = 0; t < 16; t++) {
        s[t][0] = __expf((s[t][0] - m0) * 0.125f); sum0 += s[t][0];
        s[t][1] = __expf((s[t][1] - m0) * 0.125f); sum0 += s[t][1];
        s[t][2] = __expf((s[t][2] - m1) * 0.125f); sum1 += s[t][2];
        s[t][3] = __expf((s[t][3] - m1) * 0.125f); sum1 += s[t][3];
    }
    sum0 += __shfl_xor_sync(0xffffffffu, sum0, 1);
    sum0 += __shfl_xor_sync(0xffffffffu, sum0, 2);
    sum1 += __shfl_xor_sync(0xffffffffu, sum1, 1);
    sum1 += __shfl_xor_sync(0xffffffffu, sum1, 2);
    const float inv0 = 1.0f / sum0, inv1 = 1.0f / sum1;
#pragma unroll
    for (int t = 0; t < 16; t++) {
        s[t][0] *= inv0; s[t][1] *= inv0;
        s[t][2] *= inv1; s[t][3] *= inv1;
    }

    // ---- O = P V ----
    float o[8][4];
#pragma unroll
    for (int t = 0; t < 8; t++)
#pragma unroll
        for (int c = 0; c < 4; c++) o[t][c] = 0.0f;

#pragma unroll
    for (int kc = 0; kc < 8; kc++) {
        uint32_t a[4];
        a[0] = pack_h2(s[2 * kc][0],     s[2 * kc][1]);
        a[1] = pack_h2(s[2 * kc][2],     s[2 * kc][3]);
        a[2] = pack_h2(s[2 * kc + 1][0], s[2 * kc + 1][1]);
        a[3] = pack_h2(s[2 * kc + 1][2], s[2 * kc + 1][3]);
#pragma unroll
        for (int bp = 0; bp < 4; bp++) {
            uint32_t b[4];
            int n = bp * 16 + bn8;
            int c = kc * 2 + bcb;
            ldsm_x4(b, Vt + (uint32_t)(n * VT_STR + c * 16));
            mma_f16(o[2 * bp],     a, b);
            mma_f16(o[2 * bp + 1], a, b + 2);
        }
    }

    // ---- store fp16 attn output ----
    const int gq = lane >> 2, tq = lane & 3;
#pragma unroll
    for (int nt = 0; nt < 8; nt++) {
        const int n = nt * 8 + tq * 2;
#pragma unroll
        for (int half = 0; half < 2; half++) {
            const int row = w * 16 + gq + half * 8;
            const size_t off = ((size_t)win * 128 + row) * DD + h * 64 + n;
            *(uint32_t*)(oh + off) = pack_h2(o[nt][half * 2], o[nt][half * 2 + 1]);
        }
    }
}

// ---------------------------------------------------------------------------
// LayerNorm over D=512 (1 row per 128-thread block).  HL=true also emits a
// single fp16 plane for the following GEMM.
// ---------------------------------------------------------------------------
template <bool HL>
__global__ void __launch_bounds__(128)
ln_kernel(const float* __restrict__ x, const float* __restrict__ g,
          const float* __restrict__ b, float* __restrict__ outf,
          __half* __restrict__ oh)
{
    __shared__ float red[8];
    const int row = blockIdx.x;
    const int tid = threadIdx.x;
    const int lane = tid & 31, wid = tid >> 5;

    float4 v = *(const float4*)(x + (size_t)row * DD + tid * 4);
    float s = v.x + v.y + v.z + v.w;
#pragma unroll
    for (int o = 16; o > 0; o >>= 1) s += __shfl_xor_sync(0xffffffffu, s, o);
    if (lane == 0) red[wid] = s;
    __syncthreads();
    if (tid == 0) red[0] = red[0] + red[1] + red[2] + red[3];
    __syncthreads();
    const float mu = red[0] * (1.0f / 512.0f);

    const float d0 = v.x - mu, d1 = v.y - mu, d2 = v.z - mu, d3 = v.w - mu;
    float sq = d0*d0 + d1*d1 + d2*d2 + d3*d3;
#pragma unroll
    for (int o = 16; o > 0; o >>= 1) sq += __shfl_xor_sync(0xffffffffu, sq, o);
    __syncthreads();
    if (lane == 0) red[wid] = sq;
    __syncthreads();
    if (tid == 0) red[0] = red[0] + red[1] + red[2] + red[3];
    __syncthreads();
    const float inv = rsqrtf(red[0] * (1.0f / 512.0f) + 1e-5f);

    float4 gg = *(const float4*)(g + tid * 4);
    float4 bb = *(const float4*)(b + tid * 4);
    const float y0 = d0 * inv * gg.x + bb.x;
    const float y1 = d1 * inv * gg.y + bb.y;
    const float y2 = d2 * inv * gg.z + bb.z;
    const float y3 = d3 * inv * gg.w + bb.w;
    *(float4*)(outf + (size_t)row * DD + tid * 4) = make_float4(y0, y1, y2, y3);
    if (HL) {
        const size_t i = (size_t)row * 128 + tid;
        ((uint2*)oh)[i] = make_uint2(pack_h2(y0, y1), pack_h2(y2, y3));
    }
}

// ---------------------------------------------------------------------------
// Launch pipeline (graph-capturable)
// ---------------------------------------------------------------------------
extern "C" void kernel_launch(void* const* d_in, const int* in_sizes, int n_in,
                              void* d_out, int out_size)
{
    (void)in_sizes; (void)n_in; (void)out_size;
    const float* src  = (const float*)d_in[0];
    const float* wqkv = (const float*)d_in[1];
    const float* bqkv = (const float*)d_in[2];
    const float* wout = (const float*)d_in[3];
    const float* bout = (const float*)d_in[4];
    const float* ln1g = (const float*)d_in[5];
    const float* ln1b = (const float*)d_in[6];
    const float* w1   = (const float*)d_in[7];
    const float* b1   = (const float*)d_in[8];
    const float* w2   = (const float*)d_in[9];
    const float* b2   = (const float*)d_in[10];
    const float* ln2g = (const float*)d_in[11];
    const float* ln2b = (const float*)d_in[12];
    float* out = (float*)d_out;

    float *x1, *resb;
    __half *qh, *sh, *ah, *xh, *fh, *wq, *wo, *wu, *wd;
    cudaGetSymbolAddress((void**)&x1,   g_x1);
    cudaGetSymbolAddress((void**)&resb, g_resb);
    cudaGetSymbolAddress((void**)&qh,  g_qh);
    cudaGetSymbolAddress((void**)&sh,  g_sh);
    cudaGetSymbolAddress((void**)&ah,  g_ah);
    cudaGetSymbolAddress((void**)&xh,  g_xh);
    cudaGetSymbolAddress((void**)&fh,  g_fh);
    cudaGetSymbolAddress((void**)&wq,  g_wq);  cudaGetSymbolAddress((void**)&wo,  g_wo);
    cudaGetSymbolAddress((void**)&wu,  g_w1);  cudaGetSymbolAddress((void**)&wd,  g_w2);

    const int GEMM_SMEM = 3 * STAGE + 1024;
    cudaFuncSetAttribute(tc_gemm<1>, cudaFuncAttributeMaxDynamicSharedMemorySize, GEMM_SMEM);
    cudaFuncSetAttribute(tc_gemm<2>, cudaFuncAttributeMaxDynamicSharedMemorySize, GEMM_SMEM);
    cudaFuncSetAttribute(tc_gemm<3>, cudaFuncAttributeMaxDynamicSharedMemorySize, GEMM_SMEM);
    cudaFuncSetAttribute(attn_kernel, cudaFuncAttributeMaxDynamicSharedMemorySize, ATT_SMEM);

    // 0) conversions: src + all weights (batched) -> fp16 planes
    cvtw_kernel<<<(MT * DD / 4 + 255) / 256, 256>>>(src, sh, MT * DD / 4);
    {
        const int n0 = D3 * DD / 4, n1 = DD * DD / 4,
                  n2 = DF * DD / 4, n3 = DD * DF / 4;
        cvtw4_kernel<<<(n0 + n1 + n2 + n3 + 255) / 256, 256>>>(
            wqkv, wq, n0, wout, wo, n1, w1, wu, n2, w2, wd, n3);
    }

    // 1) QKV projection -> fp16 qkv
    tc_gemm<3><<<dim3(D3 / 128, MT / 128), 256, GEMM_SMEM>>>(
        sh, wq, bqkv, nullptr, nullptr, qh, D3, DD);
    // 2) HMMA windowed attention -> attn fp16 plane
    attn_kernel<<<dim3(MT / 128, 8), 256, ATT_SMEM>>>(qh, ah);
    // 3) out projection + residual(src) -> resb f32
    tc_gemm<2><<<dim3(DD / 128, MT / 128), 256, GEMM_SMEM>>>(
        ah, wo, bout, src, resb, nullptr, DD, DD);
    // 4) LayerNorm 1 -> x1 f32 + fp16 plane
    ln_kernel<true><<<MT, 128>>>(resb, ln1g, ln1b, x1, xh);
    // 5) FFN up + ReLU -> ff fp16 plane
    tc_gemm<1><<<dim3(DF / 128, MT / 128), 256, GEMM_SMEM>>>(
        xh, wu, b1, nullptr, nullptr, fh, DF, DD);
    // 6) FFN down + residual(x1) -> resb f32
    tc_gemm<2><<<dim3(DD / 128, MT / 128), 256, GEMM_SMEM>>>(
        fh, wd, b2, x1, resb, nullptr, DD, DF);
    // 7) LayerNorm 2 -> output
    ln_kernel<false><<<MT, 128>>>(resb, ln2g, ln2b, out, nullptr);
}